// round 13
// baseline (speedup 1.0000x reference)
#include <cuda_runtime.h>
#include <cuda_bf16.h>
#include <math.h>

typedef unsigned int u32;

#define BATCH 64
#define CH 512
#define WD 512
#define NPIX 16
#define NCOL (CH*NPIX)   /* 8192 */
#define TN 64            /* n-tile = 4 out-ch x 16 px */
#define TM 32            /* m-half per CTA */
#define KCH 64           /* k per chunk */
#define NCHUNK (CH/KCH)  /* 8 */
#define KPAD 72          /* A row pad (bf16) */
#define BPAD 72          /* B row pad (bf16) */

// ---- scratch (allocation-free rule: __device__ globals) ----
__device__ __align__(16) float g_s2[BATCH*CH];            // s^2 [b][k]
__device__ __align__(16) __nv_bfloat16 g_Sh[BATCH*CH];    // s hi [m][k]
__device__ __align__(16) __nv_bfloat16 g_Sl[BATCH*CH];    // s lo [m][k]

// ---- warp-MMA helpers (sm_80-era ISA; valid in compute_100 PTX) ----
__device__ __forceinline__ u32 smem_u32(const void* p) {
    u32 a;
    asm("{ .reg .u64 t; cvta.to.shared.u64 t, %1; cvt.u32.u64 %0, t; }" : "=r"(a) : "l"(p));
    return a;
}
__device__ __forceinline__ void ldsm_x4(u32* r, u32 addr) {
    asm volatile("ldmatrix.sync.aligned.m8n8.x4.shared.b16 {%0,%1,%2,%3}, [%4];"
        : "=r"(r[0]), "=r"(r[1]), "=r"(r[2]), "=r"(r[3]) : "r"(addr));
}
__device__ __forceinline__ void ldsm_x2_trans(u32* r, u32 addr) {
    asm volatile("ldmatrix.sync.aligned.m8n8.x2.trans.shared.b16 {%0,%1}, [%2];"
        : "=r"(r[0]), "=r"(r[1]) : "r"(addr));
}
__device__ __forceinline__ void mma16816(float* c, const u32* a, const u32* b) {
    asm volatile("mma.sync.aligned.m16n8k16.row.col.f32.bf16.bf16.f32 "
        "{%0,%1,%2,%3}, {%4,%5,%6,%7}, {%8,%9}, {%0,%1,%2,%3};"
        : "+f"(c[0]), "+f"(c[1]), "+f"(c[2]), "+f"(c[3])
        : "r"(a[0]), "r"(a[1]), "r"(a[2]), "r"(a[3]), "r"(b[0]), "r"(b[1]));
}

// ============== Kernel A: style dense + hi/lo bf16 split + s^2 ==============
__global__ __launch_bounds__(256) void style_kernel(
        const float* __restrict__ w0,
        const float* __restrict__ mod_w,
        const float* __restrict__ mod_b) {
    __shared__ float w0s[64][68];
    __shared__ float mwsT[8][68];
    const int tid = threadIdx.x;
    const int b   = tid >> 2;
    const int cl  = tid & 3;
    const int c0  = blockIdx.x * 8;

    float acc0 = 0.f, acc1 = 0.f;

    for (int kt = 0; kt < 8; kt++) {
        #pragma unroll
        for (int q = 0; q < 4; q++) {
            int idx = tid + q*256;
            int m = idx >> 4, k4 = idx & 15;
            *(float4*)&w0s[m][k4*4] =
                *(const float4*)&w0[m*WD + kt*64 + k4*4];
        }
        if (tid < 128) {
            int k = tid >> 1, hf = tid & 1;
            float4 v = *(const float4*)&mod_w[(size_t)(kt*64 + k)*CH + c0 + hf*4];
            mwsT[hf*4 + 0][k] = v.x;
            mwsT[hf*4 + 1][k] = v.y;
            mwsT[hf*4 + 2][k] = v.z;
            mwsT[hf*4 + 3][k] = v.w;
        }
        __syncthreads();
        #pragma unroll
        for (int k4 = 0; k4 < 16; k4++) {
            float4 a  = *(const float4*)&w0s[b][k4*4];
            float4 m0 = *(const float4*)&mwsT[cl    ][k4*4];
            float4 m1 = *(const float4*)&mwsT[cl + 4][k4*4];
            acc0 += a.x*m0.x + a.y*m0.y + a.z*m0.z + a.w*m0.w;
            acc1 += a.x*m1.x + a.y*m1.y + a.z*m1.z + a.w*m1.w;
        }
        __syncthreads();
    }
    const float inv = 1.0f / sqrtf((float)WD);
    #pragma unroll
    for (int hf = 0; hf < 2; hf++) {
        int c = c0 + cl + hf*4;
        float s = (hf ? acc1 : acc0)*inv + mod_b[c] + 1.0f;
        g_s2[(size_t)b*CH + c] = s*s;
        __nv_bfloat16 h = __float2bfloat16(s);
        g_Sh[(size_t)b*CH + c] = h;
        g_Sl[(size_t)b*CH + c] = __float2bfloat16(s - __bfloat162float(h));
    }
}

// ============== Kernel B: mma.sync GEMM + fused demod + epilogue ==============
// grid 256 = 128 n-tiles x 2 m-halves; 256 threads = 8 warps (2mf x 4wn).
// B stored [k][n] (contiguous build writes), consumed via ldmatrix.trans.
__global__ __launch_bounds__(256) void mma_kernel(
        const float* __restrict__ conv_w,
        const float* __restrict__ cst,
        const float* __restrict__ noise,
        const float* __restrict__ ns_ptr,
        const float* __restrict__ bias,
        float* __restrict__ out) {
    __shared__ __align__(16) __nv_bfloat16 sAh[TM*KPAD];
    __shared__ __align__(16) __nv_bfloat16 sAl[TM*KPAD];
    __shared__ __align__(16) __nv_bfloat16 sBh[KCH*BPAD];
    __shared__ __align__(16) __nv_bfloat16 sBl[KCH*BPAD];
    __shared__ __align__(16) float q_s[CH][4];   // q[k][ol]; reused as noise buf
    __shared__ float d_s[4][TM];
    __shared__ float bias_s[4];
    __shared__ float nstr_s;

    const int tid = threadIdx.x;
    const int wid = tid >> 5;
    const int lane = tid & 31;
    const int wm = wid >> 2;                 // m-frag 0..1 (16 rows each)
    const int wn = wid & 3;                  // n-quarter (16 cols)
    const int ntile = blockIdx.x >> 1;
    const int m0 = (blockIdx.x & 1) * TM;
    const int n0 = ntile * TN;
    const int o0 = n0 >> 4;

    const u32 ah_base = smem_u32(sAh);
    const u32 al_base = smem_u32(sAl);
    const u32 bh_base = smem_u32(sBh);
    const u32 bl_base = smem_u32(sBl);

    // A fragment base: row = wm*16 + (lane&15), col-half via lane>>4
    const u32 aOff = (u32)(wm*16 + (lane & 15))*(KPAD*2) + (u32)(((lane >> 4) & 1)*8)*2;
    // B (trans) row base: k-row = lane&15 (+ ks*16), col byte = n*2 added per nf
    const u32 bRow = (u32)(lane & 15)*(BPAD*2);

    const int bi = tid >> 2;                 // U-build k (input channel) 0..63
    const int ol = tid & 3;                  // U-build local out channel 0..3
    const float coef = 1.0f / sqrtf(9.0f * (float)CH);

    float acc[2][4];                         // [nf][4]
    #pragma unroll
    for (int nf = 0; nf < 2; nf++)
        #pragma unroll
        for (int e = 0; e < 4; e++) acc[nf][e] = 0.f;

    // ---- prefetch chunk 0 into regs ----
    uint4 ah4, al4;
    float w9[9];
    float4 c4[4];
    {
        int m = tid >> 3, k8 = tid & 7;      // 32 m x 8 k8
        ah4 = ((const uint4*)(g_Sh + (size_t)(m0 + m)*CH))[k8];
        al4 = ((const uint4*)(g_Sl + (size_t)(m0 + m)*CH))[k8];
        #pragma unroll
        for (int t = 0; t < 9; t++)
            w9[t] = conv_w[(size_t)t*CH*CH + (size_t)bi*CH + o0 + ol];
        const float4* cp = (const float4*)&cst[bi*NPIX];
        #pragma unroll
        for (int qd = 0; qd < 4; qd++) c4[qd] = cp[qd];
    }

    for (int ck = 0; ck < NCHUNK; ck++) {
        const int k0 = ck * KCH;
        __syncthreads();                     // A: buffers free

        // ---- store A tiles (1 uint4 each) ----
        {
            int m = tid >> 3, k8 = tid & 7;
            *(uint4*)&sAh[m*KPAD + k8*8] = ah4;
            *(uint4*)&sAl[m*KPAD + k8*8] = al4;
        }
        // ---- build B tile [k][n]: 16 contiguous n per thread ----
        {
            float wr[9], q = 0.f;
            #pragma unroll
            for (int t = 0; t < 9; t++) { float w = w9[t]*coef; wr[t] = w; q += w*w; }
            q_s[k0 + bi][ol] = q;
            float c16[NPIX];
            *(float4*)&c16[0]  = c4[0]; *(float4*)&c16[4]  = c4[1];
            *(float4*)&c16[8]  = c4[2]; *(float4*)&c16[12] = c4[3];
            u32 ph[8], pl[8];
            #pragma unroll
            for (int h = 0; h < 4; h++) {
                #pragma unroll
                for (int x2 = 0; x2 < 2; x2++) {
                    float v[2];
                    #pragma unroll
                    for (int e = 0; e < 2; e++) {
                        int x = x2*2 + e;
                        float a = 0.f;
                        #pragma unroll
                        for (int kh = 0; kh < 3; kh++) {
                            int hh = h + kh - 1;
                            if (hh < 0 || hh >= 4) continue;
                            #pragma unroll
                            for (int kw = 0; kw < 3; kw++) {
                                int xx = x + kw - 1;
                                if (xx < 0 || xx >= 4) continue;
                                a += wr[kh*3 + kw] * c16[hh*4 + xx];
                            }
                        }
                        v[e] = a;
                    }
                    __nv_bfloat16 h0 = __float2bfloat16(v[0]);
                    __nv_bfloat16 h1 = __float2bfloat16(v[1]);
                    __nv_bfloat162 hp = __nv_bfloat162(h0, h1);
                    __nv_bfloat162 lp = __nv_bfloat162(
                        __float2bfloat16(v[0] - __bfloat162float(h0)),
                        __float2bfloat16(v[1] - __bfloat162float(h1)));
                    ph[h*2 + x2] = *(u32*)&hp;
                    pl[h*2 + x2] = *(u32*)&lp;
                }
            }
            // 16 n values = 32B = 2 uint4, contiguous
            uint4* dsth = (uint4*)&sBh[bi*BPAD + ol*NPIX];
            uint4* dstl = (uint4*)&sBl[bi*BPAD + ol*NPIX];
            dsth[0] = make_uint4(ph[0], ph[1], ph[2], ph[3]);
            dsth[1] = make_uint4(ph[4], ph[5], ph[6], ph[7]);
            dstl[0] = make_uint4(pl[0], pl[1], pl[2], pl[3]);
            dstl[1] = make_uint4(pl[4], pl[5], pl[6], pl[7]);
        }
        // ---- prefetch next chunk ----
        if (ck < NCHUNK - 1) {
            const int kn = k0 + KCH;
            int m = tid >> 3, k8 = tid & 7;
            ah4 = ((const uint4*)(g_Sh + (size_t)(m0 + m)*CH + kn))[k8];
            al4 = ((const uint4*)(g_Sl + (size_t)(m0 + m)*CH + kn))[k8];
            #pragma unroll
            for (int t = 0; t < 9; t++)
                w9[t] = conv_w[(size_t)t*CH*CH + (size_t)(kn + bi)*CH + o0 + ol];
            const float4* cp = (const float4*)&cst[(kn + bi)*NPIX];
            #pragma unroll
            for (int qd = 0; qd < 4; qd++) c4[qd] = cp[qd];
        }
        __syncthreads();                     // B: tiles ready

        // ---- MMA: 4 ks x 2 nf x 3 passes (m16 x n16 per warp) ----
        #pragma unroll
        for (int ks = 0; ks < 4; ks++) {
            u32 ah[4], al[4];
            ldsm_x4(ah, ah_base + aOff + (u32)(ks*32));
            ldsm_x4(al, al_base + aOff + (u32)(ks*32));
            const u32 krow = (u32)(ks*16)*(BPAD*2) + bRow;
            #pragma unroll
            for (int nf = 0; nf < 2; nf++) {
                const u32 ncol = (u32)(wn*16 + nf*8)*2;
                u32 bh[2], bl[2];
                ldsm_x2_trans(bh, bh_base + krow + ncol);
                ldsm_x2_trans(bl, bl_base + krow + ncol);
                mma16816(acc[nf], ah, bh);
                mma16816(acc[nf], ah, bl);
                mma16816(acc[nf], al, bh);
            }
        }
    }

    // ---- fused demod: one (b, og) per thread over full k=512 (first 128 threads) ----
    float dv = 0.f;
    if (tid < 128) {
        const int db = tid & 31;
        const int dg = tid >> 5;
        float a2 = 1e-8f;
        const float4* sp = (const float4*)&g_s2[(size_t)(m0 + db)*CH];
        #pragma unroll 4
        for (int k4 = 0; k4 < CH/4; k4++) {
            float4 s2v = sp[k4];
            a2 = fmaf(s2v.x, q_s[k4*4+0][dg], a2);
            a2 = fmaf(s2v.y, q_s[k4*4+1][dg], a2);
            a2 = fmaf(s2v.z, q_s[k4*4+2][dg], a2);
            a2 = fmaf(s2v.w, q_s[k4*4+3][dg], a2);
        }
        dv = rsqrtf(a2);
    }
    __syncthreads();                         // all q_s reads done
    if (tid < 128) d_s[tid >> 5][tid & 31] = dv;
    // stage noise (reuse q_s), bias, nstr
    ((float4*)q_s)[tid] = ((const float4*)noise)[tid];   // 1024 floats
    if (tid < 4) bias_s[tid] = bias[o0 + tid];
    if (tid == 4) nstr_s = ns_ptr[0];
    __syncthreads();

    // ---- epilogue ----
    const float* nzp = (const float*)q_s;
    const float gain = 1.41421356237309515f;
    const float nstr = nstr_s;
    #pragma unroll
    for (int nf = 0; nf < 2; nf++) {
        int rowl = wm*16 + (lane >> 2);
        int colb = wn*16 + nf*8 + 2*(lane & 3);
        int ol2 = colb >> 4;
        int px = colb & 15;
        float bb = bias_s[ol2];
        #pragma unroll
        for (int hh = 0; hh < 2; hh++) {
            int ml = rowl + hh*8;
            int b = m0 + ml;
            float dvv = d_s[ol2][ml];
            float2 nz = *(const float2*)&nzp[b*NPIX + px];
            float x0 = acc[nf][hh*2 + 0] * dvv + nz.x*nstr + bb;
            float x1 = acc[nf][hh*2 + 1] * dvv + nz.y*nstr + bb;
            x0 = (x0 > 0.f ? x0 : 0.2f*x0) * gain;
            x1 = (x1 > 0.f ? x1 : 0.2f*x1) * gain;
            *(float2*)&out[(size_t)b*NCOL + n0 + colb] = make_float2(x0, x1);
        }
    }
}

extern "C" void kernel_launch(void* const* d_in, const int* in_sizes, int n_in,
                              void* d_out, int out_size) {
    const float* w0     = (const float*)d_in[0];
    const float* cst    = (const float*)d_in[1];
    const float* conv_w = (const float*)d_in[2];
    const float* mod_w  = (const float*)d_in[3];
    const float* mod_b  = (const float*)d_in[4];
    const float* noise  = (const float*)d_in[5];
    const float* nstr   = (const float*)d_in[6];
    const float* bias   = (const float*)d_in[7];
    float* out = (float*)d_out;

    style_kernel<<<64, 256>>>(w0, mod_w, mod_b);
    mma_kernel<<<(NCOL / TN) * 2, 256>>>(conv_w, cst, noise, nstr, bias, out);
}